// round 1
// baseline (speedup 1.0000x reference)
#include <cuda_runtime.h>

#define D 64
#define NB 1024

// Scratch (allocation-free rule: __device__ globals)
__device__ float g_Wt[8 * D * D];      // transposed weights, Wt[e*64+d] = W[d*64+e]
__device__ float g_emb_dise[NB * D];   // dsd output per batch

__device__ __forceinline__ float leaky(float x) {
    return x >= 0.f ? x : 0.2f * x;
}

__device__ __forceinline__ float avgw(int cnt) {
    return cnt > 0 ? 1.0f / ((float)cnt + 1e-8f) : 0.0f;
}

// ---------------------------------------------------------------------------
// K0: transpose the 8 weight matrices (out = x @ W^T  =>  out[d] = sum_e x[e]*W[d,e];
// we store Wt[e*64+d] so the inner matvec loop is coalesced across the d-lanes)
// ---------------------------------------------------------------------------
__global__ void k_transpose(const float* __restrict__ w0, const float* __restrict__ w1,
                            const float* __restrict__ w2, const float* __restrict__ w3,
                            const float* __restrict__ w4, const float* __restrict__ w5,
                            const float* __restrict__ w6, const float* __restrict__ w7) {
    const float* Ws[8] = {w0, w1, w2, w3, w4, w5, w6, w7};
    int m = blockIdx.x;
    const float* W = Ws[m];
    float* Wt = g_Wt + m * D * D;
    for (int idx = threadIdx.x; idx < D * D; idx += blockDim.x) {
        int e = idx >> 6;
        int d = idx & 63;
        Wt[idx] = W[d * D + e];
    }
}

// ---------------------------------------------------------------------------
// K1: dsd path, one block per batch element, 512 threads = 8 groups (h1) x 64 dims
// emb_s1 = leaky((es+avg_ed)@W21^T + (avg_ed*es)@W22^T)
// A = maskavg_h1(emb_s1); emb_dise = leaky((A+td)@W11^T + (A*td)@W12^T)
// ---------------------------------------------------------------------------
__global__ void __launch_bounds__(512)
k_dsd(const float* __restrict__ E_s, const float* __restrict__ E_d,
      const int* __restrict__ label, const int* __restrict__ dsd_1,
      const int* __restrict__ dsd_2) {
    int b = blockIdx.x;
    int t = threadIdx.x;
    int g = t >> 6;      // h1 group
    int d = t & 63;      // embed dim

    __shared__ float shA[8 * D];   // x1 = es + avg_ed
    __shared__ float shB[8 * D];   // x2 = avg_ed * es
    __shared__ float shE[8 * D];   // emb_s1

    int idx1 = dsd_1[b * 8 + g];
    float es = E_s[idx1 * D + d];

    float sum = 0.f;
    int cnt = 0;
    const int* p2 = dsd_2 + (b * 8 + g) * 8;
#pragma unroll
    for (int h = 0; h < 8; ++h) {
        int ix = p2[h];
        cnt += (ix != 0);
        sum += E_d[ix * D + d];
    }
    float avg = sum * avgw(cnt);
    shA[g * D + d] = es + avg;
    shB[g * D + d] = avg * es;
    __syncthreads();

    const float* W21t = g_Wt + 0 * D * D;
    const float* W22t = g_Wt + 1 * D * D;
    float acc = 0.f;
#pragma unroll 16
    for (int e = 0; e < D; ++e) {
        acc = fmaf(shA[g * D + e], W21t[e * D + d],
              fmaf(shB[g * D + e], W22t[e * D + d], acc));
    }
    shE[g * D + d] = leaky(acc);
    __syncthreads();

    if (g == 0) {
        float a = 0.f;
#pragma unroll
        for (int i = 0; i < 8; ++i) a += shE[i * D + d];
        int c1 = 0;
#pragma unroll
        for (int i = 0; i < 8; ++i) c1 += (dsd_1[b * 8 + i] != 0);
        float A = a * avgw(c1);
        float td = E_d[label[b] * D + d];
        shA[d] = A + td;
        shB[d] = A * td;
    }
    __syncthreads();

    if (g == 0) {
        const float* W11t = g_Wt + 2 * D * D;
        const float* W12t = g_Wt + 3 * D * D;
        float acc2 = 0.f;
#pragma unroll 16
        for (int e = 0; e < D; ++e) {
            acc2 = fmaf(shA[e], W11t[e * D + d],
                   fmaf(shB[e], W12t[e * D + d], acc2));
        }
        g_emb_dise[b * D + d] = leaky(acc2);
    }
}

// ---------------------------------------------------------------------------
// K2: usu path + final dot. One block per batch element, 512 threads = 8 groups
// (i = usu_1 fanout) x 64 dims. Inner 8x gather-avg rows are batched so the
// eu2 GEMM amortizes each W3 load over 8 register accumulators.
// ---------------------------------------------------------------------------
__global__ void __launch_bounds__(512)
k_usu(const float* __restrict__ E_s, const int* __restrict__ usu_1,
      const int* __restrict__ usu_2, const int* __restrict__ usu_3,
      float* __restrict__ out) {
    int b = blockIdx.x;
    int t = threadIdx.x;
    int g = t >> 6;   // i group
    int d = t & 63;

    __shared__ int shI[1024];          // all usu_3 indices for this b
    __shared__ float shX[8 * 8 * D];   // [g][j][e] staging (16 KB)
    __shared__ float sh_red[2];

    shI[t]       = usu_3[b * 1024 + t];
    shI[t + 512] = usu_3[b * 1024 + 512 + t];

    int i1 = usu_1[b * 8 + g];
    float u1 = E_s[i1 * D + d];
    __syncthreads();

    // Phase 1: gather + masked-average for all 8 j rows of this group
#pragma unroll
    for (int j = 0; j < 8; ++j) {
        const int* ip = shI + (g * 8 + j) * 16;
        float sum = 0.f;
        int cnt = 0;
#pragma unroll
        for (int k = 0; k < 16; ++k) {
            int ix = ip[k];
            cnt += (ix != 0);
            sum += E_s[ix * D + d];
        }
        shX[(g * 8 + j) * D + d] = sum * avgw(cnt);
    }
    __syncthreads();

    // Phase 2: eu2 = leaky(avg_s3 @ W3^T), j-blocked (8 rows / thread), then
    // S = maskavg_j(eu2) with the usu_2 mask
    const float* W3t = g_Wt + 4 * D * D;
    float acc[8];
#pragma unroll
    for (int j = 0; j < 8; ++j) acc[j] = 0.f;
#pragma unroll 8
    for (int e = 0; e < D; ++e) {
        float wv = W3t[e * D + d];
#pragma unroll
        for (int j = 0; j < 8; ++j)
            acc[j] = fmaf(shX[(g * 8 + j) * D + e], wv, acc[j]);
    }
    float Ssum = 0.f;
#pragma unroll
    for (int j = 0; j < 8; ++j) Ssum += leaky(acc[j]);

    int c2 = 0;
    const int* p2 = usu_2 + (b * 8 + g) * 8;
#pragma unroll
    for (int j = 0; j < 8; ++j) c2 += (p2[j] != 0);
    float S = Ssum * avgw(c2);

    __syncthreads();  // done reading shX from phase 2

    // Phase 3: es1 = leaky((u1+S)@W21u^T + (S*u1)@W22u^T)
    shX[(g * 8 + 0) * D + d] = u1 + S;
    shX[(g * 8 + 1) * D + d] = S * u1;
    __syncthreads();

    const float* W21t = g_Wt + 5 * D * D;
    const float* W22t = g_Wt + 6 * D * D;
    float a2 = 0.f;
#pragma unroll 8
    for (int e = 0; e < D; ++e) {
        a2 = fmaf(shX[(g * 8 + 0) * D + e], W21t[e * D + d],
             fmaf(shX[(g * 8 + 1) * D + e], W22t[e * D + d], a2));
    }
    shX[(g * 8 + 2) * D + d] = leaky(a2);  // row g*8+2 is not read by any matvec
    __syncthreads();

    // Phase 4: T = maskavg_i(es1); emb_user = leaky(T @ W1u^T); dot with emb_dise
    if (g == 0) {
        float tsum = 0.f;
#pragma unroll
        for (int i = 0; i < 8; ++i) tsum += shX[(i * 8 + 2) * D + d];
        int c1 = 0;
#pragma unroll
        for (int i = 0; i < 8; ++i) c1 += (usu_1[b * 8 + i] != 0);
        shX[d] = tsum * avgw(c1);
    }
    __syncthreads();

    if (g == 0) {
        const float* W1t = g_Wt + 7 * D * D;
        float a3 = 0.f;
#pragma unroll 8
        for (int e = 0; e < D; ++e)
            a3 = fmaf(shX[e], W1t[e * D + d], a3);
        float eu = leaky(a3);
        float v = eu * g_emb_dise[b * D + d];
#pragma unroll
        for (int o = 16; o > 0; o >>= 1)
            v += __shfl_down_sync(0xffffffffu, v, o);
        if ((d & 31) == 0) sh_red[d >> 5] = v;
    }
    __syncthreads();
    if (t == 0) out[b] = sh_red[0] + sh_red[1];
}

// ---------------------------------------------------------------------------
extern "C" void kernel_launch(void* const* d_in, const int* in_sizes, int n_in,
                              void* d_out, int out_size) {
    const float* E_s = (const float*)d_in[0];
    const float* E_d = (const float*)d_in[1];
    // weights in metadata order: W_dsd_21, W_dsd_22, W_dsd_11, W_dsd_12,
    //                            W_usu_3, W_usu_21, W_usu_22, W_usu_1
    k_transpose<<<8, 256>>>((const float*)d_in[2], (const float*)d_in[3],
                            (const float*)d_in[4], (const float*)d_in[5],
                            (const float*)d_in[6], (const float*)d_in[7],
                            (const float*)d_in[8], (const float*)d_in[9]);

    const int* label = (const int*)d_in[10];
    const int* dsd_1 = (const int*)d_in[11];
    const int* dsd_2 = (const int*)d_in[12];
    const int* usu_1 = (const int*)d_in[13];
    const int* usu_2 = (const int*)d_in[14];
    const int* usu_3 = (const int*)d_in[15];

    k_dsd<<<NB, 512>>>(E_s, E_d, label, dsd_1, dsd_2);
    k_usu<<<NB, 512>>>(E_s, usu_1, usu_2, usu_3, (float*)d_out);
}